// round 11
// baseline (speedup 1.0000x reference)
#include <cuda_runtime.h>
#include <math.h>

#define N_    256
#define B_    64
#define FIN   5
#define NE_   65536
typedef unsigned long long u64;

// ---------------- scratch (no allocations allowed) ----------------
__device__ __align__(16) float g_mats[4 * NE_];   // [A, M0z, M1z, M2z]
__device__ __align__(16) float g_X0[320 * N_];    // ping  [c=b*5+f][node]
__device__ __align__(16) float g_X1[320 * N_];    // pong
__device__ float g_dis[N_];
__device__ float g_logits[3];                     // logits / (0.6*ln2)
__device__ unsigned g_bar;

// ---------------- packed f32x2 helpers ----------------
static __device__ __forceinline__ u64 ffma2(u64 a, u64 b, u64 c) {
    u64 d;
    asm("fma.rn.f32x2 %0, %1, %2, %3;" : "=l"(d) : "l"(a), "l"(b), "l"(c));
    return d;
}
static __device__ __forceinline__ u64 fadd2(u64 a, u64 b) {
    u64 d;
    asm("add.rn.f32x2 %0, %1, %2;" : "=l"(d) : "l"(a), "l"(b));
    return d;
}
static __device__ __forceinline__ u64 dup2(float v) {
    u64 d; unsigned u = __float_as_uint(v);
    asm("mov.b64 %0, {%1, %1};" : "=l"(d) : "r"(u));
    return d;
}
static __device__ __forceinline__ float2 unpack2(u64 v) {
    unsigned lo, hi;
    asm("mov.b64 {%0, %1}, %2;" : "=r"(lo), "=r"(hi) : "l"(v));
    return make_float2(__uint_as_float(lo), __uint_as_float(hi));
}

// ---------------- FMA-pipe transcendentals ----------------
static __device__ __forceinline__ float fast_lg2(float x) {
    int b = __float_as_int(x);
    int i = (b - 0x3f3504f3) & 0xff800000;
    float m = __int_as_float(b - i);
    float e = (float)(i >> 23);
    float t = m - 1.0f, z = t * t;
    float p =  7.0376836292e-2f;
    p = p * t - 1.1514610310e-1f;
    p = p * t + 1.1676998740e-1f;
    p = p * t - 1.2420140846e-1f;
    p = p * t + 1.4249322787e-1f;
    p = p * t - 1.6668057665e-1f;
    p = p * t + 2.0000714765e-1f;
    p = p * t - 2.4999993993e-1f;
    p = p * t + 3.3333331174e-1f;
    float lnm = t + (t * z * p - 0.5f * z);
    return e + lnm * 1.4426950409f;
}
static __device__ __forceinline__ float fast_ex2(float v) {
    v = fminf(fmaxf(v, -100.0f), 100.0f);
    int iv = __float2int_rd(v);
    float f = v - (float)iv;
    float p = 1.52527338e-5f;
    p = p * f + 1.54035304e-4f;
    p = p * f + 1.33335581e-3f;
    p = p * f + 9.61812911e-3f;
    p = p * f + 5.55041087e-2f;
    p = p * f + 2.40226507e-1f;
    p = p * f + 6.93147181e-1f;
    p = p * f + 1.0f;
    return p * __int_as_float((iv + 127) << 23);
}
static __device__ __forceinline__ float fast_rcp(float d) {
    float r = __int_as_float(0x7EF311C3 - __float_as_int(d));
    r = r * (2.0f - d * r);
    r = r * (2.0f - d * r);
    r = r * (2.0f - d * r);
    return r;
}
static __device__ float digamma_f(float x) {
    float r = 0.0f;
    while (x < 8.0f) { r -= fast_rcp(x); x += 1.0f; }
    float f = fast_rcp(x * x);
    float s = f * (1.0f / 12.0f - f * (1.0f / 120.0f - f * (1.0f / 252.0f
            - f * (1.0f / 240.0f - f * (1.0f / 132.0f)))));
    return r + 0.6931471806f * fast_lg2(x) - 0.5f * fast_rcp(x) - s;
}

// ---------------- grid-wide barrier (all 128 CTAs resident) ----------------
static __device__ __forceinline__ void grid_bar(unsigned target) {
    __syncthreads();
    if (threadIdx.x == 0) {
        unsigned one = 1u;
        asm volatile("red.release.gpu.add.u32 [%0], %1;" :: "l"(&g_bar), "r"(one) : "memory");
        unsigned v;
        do {
            asm volatile("ld.acquire.gpu.u32 %0, [%1];" : "=r"(v) : "l"(&g_bar) : "memory");
            if (v >= target) break;
            __nanosleep(64);
        } while (1);
    }
    __syncthreads();
}

__global__ void reset_kernel() { g_bar = 0; }

// ---------------- the fused persistent kernel --------------------------------
// grid 128 = 16 c-tiles(20 feature-rows) x 8 j-tiles(32 cols), 512 threads.
// smem: Ks0 [0,32768) Ks1 [32768,65536) Xs [65536,86336) Xd [86336,131392)
//       Ps [131392,172480)
#define SMEM_TOT 172480

__global__ void __launch_bounds__(512, 1) fused_kernel(
        const float* __restrict__ x,     const float* __restrict__ ewp,
        const float* __restrict__ a_uc,  const float* __restrict__ b_uc,
        const float* __restrict__ u_pi,  const float* __restrict__ u_rb,
        const float* __restrict__ lin_w, const float* __restrict__ lin_b,
        const float* __restrict__ fc_w,  const float* __restrict__ fc_b,
        float* __restrict__ out) {
    extern __shared__ __align__(16) char sm[];
    float* Xs = (float*)(sm + 65536);         // [20][260] f32
    u64*   Xd = (u64*)  (sm + 86336);         // [256][22] u64 (dup2'd X)
    u64*   Ps = (u64*)  (sm + 131392);        // [16][321] u64 partials

    const int t   = threadIdx.x;
    const int bid = blockIdx.x;
    const int c0  = (bid >> 3) * 20;
    const int j0  = (bid & 7) * 32;

    // ---- PHASE A: deg (CTAs 0..15), scalars (CTA 16), X transpose (64..127)
    if (bid < 16) {
        int w = t >> 5, l = t & 31;
        int r = bid * 16 + w;
        float s = 0.f;
        #pragma unroll
        for (int jj = 0; jj < 8; jj++) {
            int j = l + jj * 32;
            int hi = max(r, j), lo = min(r, j);
            s += fabsf(ewp[(hi * (hi + 1)) / 2 + lo]);
        }
        #pragma unroll
        for (int o = 16; o > 0; o >>= 1) s += __shfl_xor_sync(0xffffffffu, s, o);
        if (l == 0) g_dis[r] = (s > 0.f) ? rsqrtf(s) : 0.f;
    } else if (bid == 16) {
        __shared__ float kld_s[3];
        if (t < 3) {
            const float LOG2E = 1.4426950409f, LN2 = 0.6931471806f;
            float au = fmaxf(a_uc[t], -10.f);
            float bu = fminf(fmaxf(b_uc[t], -10.f), 50.f);
            float a  = LN2 * fast_lg2(1.f + fast_ex2(au * LOG2E));
            float bb = LN2 * fast_lg2(1.f + fast_ex2(bu * LOG2E));
            float up = fminf(fmaxf(u_pi[t], 1e-6f), 1.f - 1e-6f);
            float t1 = fast_ex2(fast_lg2(up) * fast_rcp(bb));        // up^(1/b)
            float pi = fast_ex2(fast_lg2(1.f - t1) * fast_rcp(a));   // ^(1/a)
            g_logits[t] = (fast_lg2(pi) - fast_lg2(1.f - pi)) * (1.f / 0.6f);
            out[193 + t] = pi;   // drop_rates
            const float euler = 0.577215664901532f;
            kld_s[t] = (1.f - 0.8f * fast_rcp(a)) * (-euler - digamma_f(bb) - fast_rcp(bb))
                     + LN2 * fast_lg2(a * bb + 1e-10f) - (-0.22314355f)
                     - (bb - 1.f) * fast_rcp(bb);
        }
        __syncthreads();
        if (t == 0) out[192] = kld_s[0] + kld_s[1] + kld_s[2];   // kld_loss
    } else if (bid >= 64) {
        int b = bid - 64;
        if (t < 256) {
            const float* xb = x + (b * 256 + t) * FIN;
            #pragma unroll
            for (int f = 0; f < FIN; f++)
                g_X0[(b * FIN + f) * 256 + t] = xb[f];
        }
    }
    grid_bar(128);

    // ---- PHASE B: build [A, M0z, M1z, M2z] — exactly ONE element per thread
    // (128 CTAs x 512 threads = 65536 = NE_)
    {
        int e = (bid << 9) + t;
        int ii = e >> 8, jj = e & 255;
        int hi = max(ii, jj), lo = min(ii, jj);
        float w = ewp[(hi * (hi + 1)) / 2 + lo];
        float aij = __ldcg(&g_dis[ii]) * w * __ldcg(&g_dis[jj]);
        g_mats[e] = aij;
        #pragma unroll
        for (int l = 0; l < 3; l++) {
            float ur = u_rb[l * NE_ + e];
            ur = fminf(fmaxf(ur, 1e-6f), 1.0f - 1e-6f);
            float L = (fast_lg2(ur) - fast_lg2(1.0f - ur)) * (1.0f / 0.6f);
            float v = -(__ldcg(&g_logits[l]) + L);
            float z = fast_rcp(1.0f + fast_ex2(v));
            g_mats[(l + 1) * NE_ + e] = z * aij;
        }
    }
    grid_bar(256);

    // ---- PHASE C: 5 conv stages
    auto issue_M = [&](const float* Msrc, int buf) {
        char* base = sm + buf * 32768;
        #pragma unroll
        for (int i = 0; i < 4; i++) {
            int idx = i * 512 + t;                 // 2048 chunks of 16B
            int row = idx >> 3, ch = idx & 7;
            const float* src = Msrc + row * 256 + j0 + ch * 4;
            unsigned dst = (unsigned)__cvta_generic_to_shared(base + row * 128 + ch * 16);
            asm volatile("cp.async.cg.shared.global [%0], [%1], 16;" :: "r"(dst), "l"(src));
        }
        asm volatile("cp.async.commit_group;" ::: "memory");
    };
    auto issue_X = [&](const float* Xsrc) {
        #pragma unroll
        for (int i = 0; i < 3; i++) {
            int idx = i * 512 + t;                 // 1280 chunks of 16B
            if (idx < 1280) {
                int row = idx >> 6, ch = idx & 63;
                const float* src = Xsrc + (c0 + row) * 256 + ch * 4;
                unsigned dst = (unsigned)__cvta_generic_to_shared((char*)Xs + row * 1040 + ch * 16);
                asm volatile("cp.async.cg.shared.global [%0], [%1], 16;" :: "r"(dst), "l"(src));
            }
        }
        asm volatile("cp.async.commit_group;" ::: "memory");
    };

    const int midx[5] = {1, 0, 2, 0, 3};   // M0z, A, M1z, A, M2z
    issue_M(g_mats + midx[0] * NE_, 0);
    issue_M(g_mats + midx[1] * NE_, 1);
    issue_X(g_X0);

    #pragma unroll 1
    for (int s = 0; s < 5; s++) {
        asm volatile("cp.async.wait_group 0;" ::: "memory");
        __syncthreads();

        // prepass: Xs[c][k] -> Xd[k][c] (dup2)
        {
            int kk = t & 255, hh = t >> 8;
            #pragma unroll
            for (int c = 0; c < 10; c++)
                Xd[kk * 22 + hh * 10 + c] = dup2(Xs[(hh * 10 + c) * 260 + kk]);
        }
        __syncthreads();

        // compute: warp w = k-split (16 k's), lane = (cg of 10 c's, j2 col-pair)
        {
            int w = t >> 5, l = t & 31, j2 = l & 15, cg = l >> 4;
            const float* ksb = (const float*)(sm + (s & 1) * 32768);
            u64 acc[10];
            #pragma unroll
            for (int i2 = 0; i2 < 10; i2++) acc[i2] = 0ull;
            int kb = w * 16;
            #pragma unroll 4
            for (int k = kb; k < kb + 16; k++) {
                u64 kq = *(const u64*)&ksb[k * 32 + j2 * 2];
                const u64* xr = &Xd[k * 22 + cg * 10];
                ulonglong2 xa = *(const ulonglong2*)(xr);
                ulonglong2 xb = *(const ulonglong2*)(xr + 2);
                ulonglong2 xc = *(const ulonglong2*)(xr + 4);
                ulonglong2 xd = *(const ulonglong2*)(xr + 6);
                ulonglong2 xe = *(const ulonglong2*)(xr + 8);
                acc[0] = ffma2(kq, xa.x, acc[0]);  acc[1] = ffma2(kq, xa.y, acc[1]);
                acc[2] = ffma2(kq, xb.x, acc[2]);  acc[3] = ffma2(kq, xb.y, acc[3]);
                acc[4] = ffma2(kq, xc.x, acc[4]);  acc[5] = ffma2(kq, xc.y, acc[5]);
                acc[6] = ffma2(kq, xd.x, acc[6]);  acc[7] = ffma2(kq, xd.y, acc[7]);
                acc[8] = ffma2(kq, xe.x, acc[8]);  acc[9] = ffma2(kq, xe.y, acc[9]);
            }
            u64* pp = &Ps[w * 321 + l * 10];
            #pragma unroll
            for (int i2 = 0; i2 < 10; i2++) pp[i2] = acc[i2];
        }
        __syncthreads();

        // combine 16 k-splits + 0.1*x + 0.45*agg (+relu on stage 2), store Y
        float* wrb = (s & 1) ? g_X0 : g_X1;
        if (t < 320) {
            int c = t >> 4, j2c = t & 15;
            int lane = ((c >= 10) ? 16 : 0) + j2c;
            int i2 = (c >= 10) ? (c - 10) : c;
            u64 s0 = 0ull, s1 = 0ull;
            #pragma unroll
            for (int w2 = 0; w2 < 16; w2 += 2) {
                s0 = fadd2(s0, Ps[w2 * 321 + lane * 10 + i2]);
                s1 = fadd2(s1, Ps[(w2 + 1) * 321 + lane * 10 + i2]);
            }
            float2 sv = unpack2(fadd2(s0, s1));
            int jj = j0 + 2 * j2c;
            float y0 = 0.1f * Xs[c * 260 + jj]     + 0.45f * sv.x;
            float y1 = 0.1f * Xs[c * 260 + jj + 1] + 0.45f * sv.y;
            if (s == 2) { y0 = fmaxf(y0, 0.f); y1 = fmaxf(y1, 0.f); }
            float2 yy; yy.x = y0; yy.y = y1;
            *(float2*)&wrb[(c0 + c) * 256 + jj] = yy;
        }
        if (s < 3) issue_M(g_mats + midx[s + 2] * NE_, s & 1);   // static prefetch
        grid_bar(128 * (3 + s));
        if (s < 4) issue_X(wrb);                                  // fresh X
    }

    // ---- PHASE D: head (CTAs 0..63, graph b = bid), o lives in g_X1
    if (bid < 64) {
        float* Os   = Xs;                       // reuse [5][260]
        float* Pool = (float*)(sm + 86336);     // reuse Xd area [4][128]
        #pragma unroll
        for (int i = 0; i < 3; i++) {
            int idx = i * 512 + t;
            if (idx < 1280) {
                int f = idx >> 8, n = idx & 255;
                Os[f * 260 + n] = __ldcg(&g_X1[(bid * FIN + f) * 256 + n]);
            }
        }
        __syncthreads();
        {
            int k = t & 127, h = t >> 7;
            u64 lw[FIN];
            #pragma unroll
            for (int f = 0; f < FIN; f++) lw[f] = dup2(lin_w[f * 128 + k]);
            u64 lb2 = dup2(lin_b[k]);
            float s2 = 0.f;
            int n0 = h * 64;
            #pragma unroll 4
            for (int n = n0; n < n0 + 64; n += 2) {
                u64 v2 = lb2;
                #pragma unroll
                for (int f = 0; f < FIN; f++)
                    v2 = ffma2(*(const u64*)&Os[f * 260 + n], lw[f], v2);
                float2 vv = unpack2(v2);
                s2 += fmaxf(vv.x, 0.f) + fmaxf(vv.y, 0.f);
            }
            Pool[h * 128 + k] = s2;
        }
        __syncthreads();
        if (t < 3) {
            float s2 = fc_b[t];
            for (int k2 = 0; k2 < 128; k2++)
                s2 = fmaf(Pool[k2] + Pool[128 + k2] + Pool[256 + k2] + Pool[384 + k2],
                          fc_w[k2 * 3 + t], s2);
            out[bid * 3 + t] = s2;
        }
    }
}

// ---------------- launch ----------------
extern "C" void kernel_launch(void* const* d_in, const int* in_sizes, int n_in,
                              void* d_out, int out_size) {
    const float* x     = (const float*)d_in[0];
    const float* ewp   = (const float*)d_in[1];
    const float* a_uc  = (const float*)d_in[2];
    const float* b_uc  = (const float*)d_in[3];
    const float* u_pi  = (const float*)d_in[4];
    const float* u_rb  = (const float*)d_in[5];
    const float* lin_w = (const float*)d_in[6];
    const float* lin_b = (const float*)d_in[7];
    const float* fc_w  = (const float*)d_in[8];
    const float* fc_b  = (const float*)d_in[9];
    // d_in[10] = edge_index, d_in[11] = batch: structure is analytic, unused.
    float* out = (float*)d_out;

    cudaFuncSetAttribute(fused_kernel,
                         cudaFuncAttributeMaxDynamicSharedMemorySize, SMEM_TOT);

    reset_kernel<<<1, 1>>>();
    fused_kernel<<<128, 512, SMEM_TOT>>>(x, ewp, a_uc, b_uc, u_pi, u_rb,
                                         lin_w, lin_b, fc_w, fc_b, out);
}

// round 12
// speedup vs baseline: 1.7940x; 1.7940x over previous
#include <cuda_runtime.h>
#include <math.h>

#define N_    256
#define B_    64
#define FIN   5
#define NE_   65536

// ---------------- scratch (no allocations allowed) ----------------
__device__ __align__(16) float g_S[4 * NE_];   // S0, SA, S1, S2  (0.1I + 0.45*M)
__device__ __align__(16) float g_P[NE_];       // P  = S0*SA
__device__ __align__(16) float g_G[NE_];       // K2 = SA*S2
__device__ float g_dis[N_];
__device__ float g_logits[3];                  // logits / (0.6*ln2)

// ---------------- packed f32x2 helpers ----------------
static __device__ __forceinline__ unsigned long long ffma2(unsigned long long a,
                                                           unsigned long long b,
                                                           unsigned long long c) {
    unsigned long long d;
    asm("fma.rn.f32x2 %0, %1, %2, %3;" : "=l"(d) : "l"(a), "l"(b), "l"(c));
    return d;
}
static __device__ __forceinline__ unsigned long long fadd2(unsigned long long a,
                                                           unsigned long long b) {
    unsigned long long d;
    asm("add.rn.f32x2 %0, %1, %2;" : "=l"(d) : "l"(a), "l"(b));
    return d;
}
static __device__ __forceinline__ unsigned long long dup2(float v) {
    unsigned long long d;
    unsigned int u = __float_as_uint(v);
    asm("mov.b64 %0, {%1, %1};" : "=l"(d) : "r"(u));
    return d;
}
static __device__ __forceinline__ float2 unpack2(unsigned long long v) {
    unsigned int lo, hi;
    asm("mov.b64 {%0, %1}, %2;" : "=r"(lo), "=r"(hi) : "l"(v));
    return make_float2(__uint_as_float(lo), __uint_as_float(hi));
}

// ---------------- FMA-pipe transcendentals (no MUFU, no software powf) --------
static __device__ __forceinline__ float fast_lg2(float x) {
    int b = __float_as_int(x);
    int i = (b - 0x3f3504f3) & 0xff800000;
    float m = __int_as_float(b - i);
    float e = (float)(i >> 23);
    float t = m - 1.0f, z = t * t;
    float p =  7.0376836292e-2f;
    p = p * t - 1.1514610310e-1f;
    p = p * t + 1.1676998740e-1f;
    p = p * t - 1.2420140846e-1f;
    p = p * t + 1.4249322787e-1f;
    p = p * t - 1.6668057665e-1f;
    p = p * t + 2.0000714765e-1f;
    p = p * t - 2.4999993993e-1f;
    p = p * t + 3.3333331174e-1f;
    float lnm = t + (t * z * p - 0.5f * z);
    return e + lnm * 1.4426950409f;
}
static __device__ __forceinline__ float fast_ex2(float v) {
    v = fminf(fmaxf(v, -100.0f), 100.0f);
    int iv = __float2int_rd(v);
    float f = v - (float)iv;
    float p = 1.52527338e-5f;
    p = p * f + 1.54035304e-4f;
    p = p * f + 1.33335581e-3f;
    p = p * f + 9.61812911e-3f;
    p = p * f + 5.55041087e-2f;
    p = p * f + 2.40226507e-1f;
    p = p * f + 6.93147181e-1f;
    p = p * f + 1.0f;
    return p * __int_as_float((iv + 127) << 23);
}
static __device__ __forceinline__ float fast_rcp(float d) {
    float r = __int_as_float(0x7EF311C3 - __float_as_int(d));
    r = r * (2.0f - d * r);
    r = r * (2.0f - d * r);
    r = r * (2.0f - d * r);
    return r;
}
static __device__ float digamma_f(float x) {
    float r = 0.0f;
    while (x < 8.0f) { r -= fast_rcp(x); x += 1.0f; }
    float f = fast_rcp(x * x);
    float s = f * (1.0f / 12.0f - f * (1.0f / 120.0f - f * (1.0f / 252.0f
            - f * (1.0f / 240.0f - f * (1.0f / 132.0f)))));
    return r + 0.6931471806f * fast_lg2(x) - 0.5f * fast_rcp(x) - s;
}

// ---------------- kernel 1: degree/dis (32 blocks) + fast scalar block (32) ---
__global__ void __launch_bounds__(256) deg_scalar_kernel(
        const float* __restrict__ ewp,
        const float* __restrict__ a_uc,
        const float* __restrict__ b_uc,
        const float* __restrict__ u_pi,
        float* __restrict__ out) {
    int b = blockIdx.x, t = threadIdx.x;
    if (b == 32) {   // scalar-only block, fully FMA-pipe (validated R7/R9/R11)
        __shared__ float kld_s[3];
        if (t < 3) {
            const float LOG2E = 1.4426950409f, LN2 = 0.6931471806f;
            float au = fmaxf(a_uc[t], -10.f);
            float bu = fminf(fmaxf(b_uc[t], -10.f), 50.f);
            float a  = LN2 * fast_lg2(1.f + fast_ex2(au * LOG2E));
            float bb = LN2 * fast_lg2(1.f + fast_ex2(bu * LOG2E));
            float up = fminf(fmaxf(u_pi[t], 1e-6f), 1.f - 1e-6f);
            float t1 = fast_ex2(fast_lg2(up) * fast_rcp(bb));        // up^(1/b)
            float pi = fast_ex2(fast_lg2(1.f - t1) * fast_rcp(a));   // (...)^(1/a)
            g_logits[t] = (fast_lg2(pi) - fast_lg2(1.f - pi)) * (1.f / 0.6f);
            out[193 + t] = pi;   // drop_rates
            const float euler = 0.577215664901532f;
            kld_s[t] = (1.f - 0.8f * fast_rcp(a)) * (-euler - digamma_f(bb) - fast_rcp(bb))
                     + LN2 * fast_lg2(a * bb + 1e-10f) + 0.22314355f
                     - (bb - 1.f) * fast_rcp(bb);
        }
        __syncthreads();
        if (t == 0) out[192] = kld_s[0] + kld_s[1] + kld_s[2];   // kld_loss
        return;
    }
    // degree: warp w handles row r = b*8+w
    int w = t >> 5, l = t & 31;
    int r = b * 8 + w;
    float s = 0.f;
    #pragma unroll
    for (int jj = 0; jj < 8; jj++) {
        int j = l + jj * 32;
        int hi = max(r, j), lo = min(r, j);
        s += fabsf(ewp[(hi * (hi + 1)) / 2 + lo]);
    }
    #pragma unroll
    for (int o = 16; o > 0; o >>= 1) s += __shfl_xor_sync(0xffffffffu, s, o);
    if (l == 0) g_dis[r] = (s > 0.f) ? rsqrtf(s) : 0.f;
}

// ---------------- kernel 2: build S matrices (0.1I + 0.45*M), fast sigmoid ----
__global__ void __launch_bounds__(256) mats_kernel(const float* __restrict__ ewp,
                                                   const float* __restrict__ u_rb) {
    int i = blockIdx.x, j = threadIdx.x;
    int r = max(i, j), c = min(i, j);
    float w = ewp[(r * (r + 1)) / 2 + c];
    float aij = g_dis[i] * w * g_dis[j];
    int e = i * N_ + j;
    float diag = (i == j) ? 0.1f : 0.0f;
    g_S[1 * NE_ + e] = 0.45f * aij + diag;                        // SA
    #pragma unroll
    for (int l = 0; l < 3; l++) {
        float ur = u_rb[l * NE_ + e];
        ur = fminf(fmaxf(ur, 1e-6f), 1.0f - 1e-6f);
        float L = (fast_lg2(ur) - fast_lg2(1.0f - ur)) * (1.0f / 0.6f);
        float v = -(g_logits[l] + L);
        float z = fast_rcp(1.0f + fast_ex2(v));
        int slot = (l == 0) ? 0 : (l + 1);                        // S0, S1, S2
        g_S[slot * NE_ + e] = 0.45f * z * aij + diag;
    }
}

// ---------------- kernel 3: dual 256x256x256 fp32 GEMM (tile 32x32) -----------
// grid 128: bx>>6 selects (A,B,C) triple; both GEMMs are independent.
#define GEMM_SMEM (33280 + 32768)
__global__ void __launch_bounds__(256) gemm_kernel(
        const float* __restrict__ A0, const float* __restrict__ B0, float* __restrict__ C0,
        const float* __restrict__ A1, const float* __restrict__ B1, float* __restrict__ C1) {
    extern __shared__ __align__(16) char gsm[];
    float*  As = (float*)gsm;                 // [32][260] padded
    float4* Bs = (float4*)(gsm + 33280);      // [256][8]

    int bx = blockIdx.x;
    int g = bx >> 6, tile = bx & 63;
    const float* A = g ? A1 : A0;
    const float* B = g ? B1 : B0;
    float*       C = g ? C1 : C0;
    int tr = tile >> 3, tc = tile & 7;
    int t = threadIdx.x;

    #pragma unroll
    for (int it = 0; it < 8; it++) {
        int idx = t + it * 256;
        int r = idx >> 6, k4 = (idx & 63) << 2;
        *(float4*)&As[r * 260 + k4] = *(const float4*)&A[(tr * 32 + r) * 256 + k4];
        int rowk = idx >> 3, c4 = idx & 7;
        Bs[rowk * 8 + c4] = *(const float4*)&B[rowk * 256 + tc * 32 + c4 * 4];
    }
    __syncthreads();

    int r = t >> 3, c8 = t & 7;
    unsigned long long acc0 = 0ull, acc1 = 0ull;
    const float* arow = &As[r * 260];
    #pragma unroll 1
    for (int k0 = 0; k0 < 256; k0 += 8) {
        float a[8];
        ulonglong2 bv[8];
        #pragma unroll
        for (int u = 0; u < 8; u++) a[u] = arow[k0 + u];
        #pragma unroll
        for (int u = 0; u < 8; u++) bv[u] = *(const ulonglong2*)&Bs[(k0 + u) * 8 + c8];
        #pragma unroll
        for (int u = 0; u < 8; u++) {
            unsigned long long ad = dup2(a[u]);
            acc0 = ffma2(ad, bv[u].x, acc0);
            acc1 = ffma2(ad, bv[u].y, acc1);
        }
    }
    float2 a0 = unpack2(acc0), a1 = unpack2(acc1);
    float4 res = make_float4(a0.x, a0.y, a1.x, a1.y);
    *(float4*)&C[(tr * 32 + r) * 256 + tc * 32 + c8 * 4] = res;
}

// ---------------- kernel 4: 3-stage conv + head, clustered --------------------
// 128 blocks = (graph b = blockIdx.x>>1, column half c = blockIdx.x&1),
// cluster (2,1,1), 512 threads.
// stage 0: t = P^T x;  stage 1: x3 = relu(S1^T t);  stage 2: o = K2^T x3.
#define SM_MTILE   0          // 2 * 128*128 f32 = 131072
#define SM_XD      131072     // 256*6 u64       = 12288
#define SM_XP      143360     // 256*5 f32       = 5120
#define SM_PS      148480     // 512*11 u64      = 45056
#define SM_POOL    193536     // 512 f32         = 2048
#define SM_POOLP   195584     // 128 f32         = 512
#define SM_TOTAL   196096

__global__ void __launch_bounds__(512, 1) __cluster_dims__(2, 1, 1)
conv_head_kernel(const float* __restrict__ x,
                 const float* __restrict__ lin_w, const float* __restrict__ lin_b,
                 const float* __restrict__ fc_w,  const float* __restrict__ fc_b,
                 float* __restrict__ out) {
    extern __shared__ __align__(16) char sm_[];
    float*              Mtile = (float*)(sm_ + SM_MTILE);
    unsigned long long* Xd    = (unsigned long long*)(sm_ + SM_XD);
    float*              Xp    = (float*)(sm_ + SM_XP);
    unsigned long long* Ps    = (unsigned long long*)(sm_ + SM_PS);
    float*              Pool  = (float*)(sm_ + SM_POOL);
    float*              PoolP = (float*)(sm_ + SM_POOLP);

    const int t  = threadIdx.x;
    const int j4 = t & 31;
    const int q  = t >> 5;
    const int b  = blockIdx.x >> 1;
    const int c  = blockIdx.x & 1;
    const unsigned prank = (unsigned)(c ^ 1);

    const float* stage_mat[3] = { g_P, g_S + 2 * NE_, g_G };

    auto issue_half = [&](const float* gsrc, float* stile) {
        #pragma unroll
        for (int k = 0; k < 8; k++) {
            int o = (k << 9) + t;
            int row = o >> 5, seg = (o & 31) << 2;
            const float* src = gsrc + row * 256 + seg;
            unsigned int dst = (unsigned int)__cvta_generic_to_shared(&stile[row * 128 + seg]);
            asm volatile("cp.async.cg.shared.global [%0], [%1], 16;" :: "r"(dst), "l"(src));
        }
        asm volatile("cp.async.commit_group;" ::: "memory");
    };

    // prefetch stage 0 (P)
    {
        const float* g0 = stage_mat[0] + c * 128;
        issue_half(g0, Mtile);
        issue_half(g0 + 128 * 256, Mtile + 16384);
    }

    // load this graph's X
    {
        const float* xb = x + b * (N_ * FIN);
        for (int idx = t; idx < N_ * FIN; idx += 512) {
            float v = xb[idx];
            int i = idx / 5, f = idx - i * 5;
            Xp[idx] = v;
            Xd[i * 6 + f] = dup2(v);
        }
    }

    unsigned int peerXp, peerXd;
    {
        unsigned int lxp = (unsigned int)__cvta_generic_to_shared(Xp);
        unsigned int lxd = (unsigned int)__cvta_generic_to_shared(Xd);
        asm("mapa.shared::cluster.u32 %0, %1, %2;" : "=r"(peerXp) : "r"(lxp), "r"(prank));
        asm("mapa.shared::cluster.u32 %0, %1, %2;" : "=r"(peerXd) : "r"(lxd), "r"(prank));
    }

    unsigned long long accA[FIN], accB[FIN];
    const int qq8 = q * 8;

    #pragma unroll 1
    for (int cs = 0; cs < 3; cs++) {
        #pragma unroll
        for (int f = 0; f < FIN; f++) { accA[f] = 0ull; accB[f] = 0ull; }

        asm volatile("cp.async.wait_group 1;" ::: "memory");
        __syncthreads();

        #pragma unroll
        for (int r_ = 0; r_ < 8; r_++) {
            int row = qq8 + r_;
            ulonglong2 mv = *(const ulonglong2*)&Mtile[row * 128 + j4 * 4];
            const unsigned long long* xr = &Xd[row * 6];
            ulonglong2 x01 = *(const ulonglong2*)xr;
            ulonglong2 x23 = *(const ulonglong2*)(xr + 2);
            unsigned long long x4 = xr[4];
            accA[0] = ffma2(mv.x, x01.x, accA[0]);  accB[0] = ffma2(mv.y, x01.x, accB[0]);
            accA[1] = ffma2(mv.x, x01.y, accA[1]);  accB[1] = ffma2(mv.y, x01.y, accB[1]);
            accA[2] = ffma2(mv.x, x23.x, accA[2]);  accB[2] = ffma2(mv.y, x23.x, accB[2]);
            accA[3] = ffma2(mv.x, x23.y, accA[3]);  accB[3] = ffma2(mv.y, x23.y, accB[3]);
            accA[4] = ffma2(mv.x, x4,    accA[4]);  accB[4] = ffma2(mv.y, x4,    accB[4]);
        }

        asm volatile("cp.async.wait_group 0;" ::: "memory");
        __syncthreads();

        #pragma unroll
        for (int r_ = 0; r_ < 8; r_++) {
            int row = qq8 + r_;
            ulonglong2 mv = *(const ulonglong2*)&Mtile[16384 + row * 128 + j4 * 4];
            const unsigned long long* xr = &Xd[(128 + row) * 6];
            ulonglong2 x01 = *(const ulonglong2*)xr;
            ulonglong2 x23 = *(const ulonglong2*)(xr + 2);
            unsigned long long x4 = xr[4];
            accA[0] = ffma2(mv.x, x01.x, accA[0]);  accB[0] = ffma2(mv.y, x01.x, accB[0]);
            accA[1] = ffma2(mv.x, x01.y, accA[1]);  accB[1] = ffma2(mv.y, x01.y, accB[1]);
            accA[2] = ffma2(mv.x, x23.x, accA[2]);  accB[2] = ffma2(mv.y, x23.x, accB[2]);
            accA[3] = ffma2(mv.x, x23.y, accA[3]);  accB[3] = ffma2(mv.y, x23.y, accB[3]);
            accA[4] = ffma2(mv.x, x4,    accA[4]);  accB[4] = ffma2(mv.y, x4,    accB[4]);
        }

        {
            int base = (q * 32 + j4) * 11;
            #pragma unroll
            for (int f = 0; f < FIN; f++) { Ps[base + f] = accA[f]; Ps[base + 5 + f] = accB[f]; }
        }
        __syncthreads();

        // prefetch next stage's matrix
        if (cs < 2) {
            const float* gsrc = stage_mat[cs + 1] + c * 128;
            issue_half(gsrc, Mtile);
            issue_half(gsrc + 128 * 256, Mtile + 16384);
        }

        // combine 16 K-splits; relu on stage 1; peer exchange on stages 0,1
        if (t < 320) {
            int f = t % 5, pc = t / 5;
            int j4c = pc >> 1, a = pc & 1;
            unsigned long long s = Ps[j4c * 11 + a * 5 + f];
            #pragma unroll
            for (int qq = 1; qq < 16; qq++)
                s = fadd2(s, Ps[(qq * 32 + j4c) * 11 + a * 5 + f]);
            float2 sv = unpack2(s);
            float y0 = sv.x, y1 = sv.y;
            if (cs == 1) { y0 = fmaxf(y0, 0.f); y1 = fmaxf(y1, 0.f); }
            int g0c = c * 128 + 4 * j4c + 2 * a;
            Xp[g0c * 5 + f] = y0;  Xp[(g0c + 1) * 5 + f] = y1;
            if (cs < 2) {
                unsigned long long d0 = dup2(y0), d1 = dup2(y1);
                Xd[g0c * 6 + f] = d0;  Xd[(g0c + 1) * 6 + f] = d1;
                asm volatile("st.shared::cluster.f32 [%0], %1;" :: "r"(peerXp + (g0c * 5 + f) * 4), "f"(y0));
                asm volatile("st.shared::cluster.f32 [%0], %1;" :: "r"(peerXp + ((g0c + 1) * 5 + f) * 4), "f"(y1));
                asm volatile("st.shared::cluster.b64 [%0], %1;" :: "r"(peerXd + (g0c * 6 + f) * 8), "l"(d0));
                asm volatile("st.shared::cluster.b64 [%0], %1;" :: "r"(peerXd + ((g0c + 1) * 6 + f) * 8), "l"(d1));
            }
        }
        if (cs < 2) {
            asm volatile("barrier.cluster.arrive.aligned;" ::: "memory");
            asm volatile("barrier.cluster.wait.aligned;" ::: "memory");
        } else {
            __syncthreads();
        }
    }

    // ---- head: relu(o @ lin_w + lin_b), pool over this block's 128 nodes ----
    {
        int k = t & 127, h2 = t >> 7;
        float lw0 = lin_w[k], lw1 = lin_w[128 + k], lw2 = lin_w[256 + k],
              lw3 = lin_w[384 + k], lw4 = lin_w[512 + k];
        float lb = lin_b[k];
        float s = 0.f;
        int n0 = c * 128 + h2 * 32;
        for (int n = n0; n < n0 + 32; n++) {
            const float* xr = &Xp[n * 5];
            float v = lb;
            v = fmaf(xr[0], lw0, v);
            v = fmaf(xr[1], lw1, v);
            v = fmaf(xr[2], lw2, v);
            v = fmaf(xr[3], lw3, v);
            v = fmaf(xr[4], lw4, v);
            s += fmaxf(v, 0.f);
        }
        Pool[h2 * 128 + k] = s;
    }
    __syncthreads();
    if (t < 128) {
        float p = Pool[t] + Pool[128 + t] + Pool[256 + t] + Pool[384 + t];
        if (c) {
            unsigned int lpp = (unsigned int)__cvta_generic_to_shared(&PoolP[t]);
            unsigned int rpp;
            asm("mapa.shared::cluster.u32 %0, %1, %2;" : "=r"(rpp) : "r"(lpp), "r"(prank));
            asm volatile("st.shared::cluster.f32 [%0], %1;" :: "r"(rpp), "f"(p));
        } else {
            Pool[t] = p;
        }
    }
    asm volatile("barrier.cluster.arrive.aligned;" ::: "memory");
    asm volatile("barrier.cluster.wait.aligned;" ::: "memory");
    if (c == 0 && t < 3) {
        float s = fc_b[t];
        for (int k2 = 0; k2 < 128; k2++)
            s = fmaf(Pool[k2] + PoolP[k2], fc_w[k2 * 3 + t], s);
        out[b * 3 + t] = s;
    }
}

// ---------------- launch ----------------
extern "C" void kernel_launch(void* const* d_in, const int* in_sizes, int n_in,
                              void* d_out, int out_size) {
    const float* x     = (const float*)d_in[0];
    const float* ewp   = (const float*)d_in[1];
    const float* a_uc  = (const float*)d_in[2];
    const float* b_uc  = (const float*)d_in[3];
    const float* u_pi  = (const float*)d_in[4];
    const float* u_rb  = (const float*)d_in[5];
    const float* lin_w = (const float*)d_in[6];
    const float* lin_b = (const float*)d_in[7];
    const float* fc_w  = (const float*)d_in[8];
    const float* fc_b  = (const float*)d_in[9];
    // d_in[10] = edge_index, d_in[11] = batch: structure is analytic, unused.
    float* out = (float*)d_out;

    cudaFuncSetAttribute(conv_head_kernel,
                         cudaFuncAttributeMaxDynamicSharedMemorySize, SM_TOTAL);
    cudaFuncSetAttribute(gemm_kernel,
                         cudaFuncAttributeMaxDynamicSharedMemorySize, GEMM_SMEM);

    float *S0, *SA, *S2, *P, *K2;
    cudaGetSymbolAddress((void**)&S0, g_S);
    SA = S0 + NE_;  S2 = S0 + 3 * NE_;
    cudaGetSymbolAddress((void**)&P,  g_P);
    cudaGetSymbolAddress((void**)&K2, g_G);

    deg_scalar_kernel<<<33, 256>>>(ewp, a_uc, b_uc, u_pi, out);
    mats_kernel<<<N_, 256>>>(ewp, u_rb);
    gemm_kernel<<<128, 256, GEMM_SMEM>>>(S0, SA, P,  SA, S2, K2);  // P = S0*SA, K2 = SA*S2
    conv_head_kernel<<<2 * B_, 512, SM_TOTAL>>>(x, lin_w, lin_b, fc_w, fc_b, out);
}

// round 13
// speedup vs baseline: 1.8452x; 1.0285x over previous
#include <cuda_runtime.h>
#include <math.h>

#define N_    256
#define B_    64
#define FIN   5
#define NE_   65536
typedef unsigned long long u64;

// ---------------- scratch (no allocations allowed) ----------------
__device__ __align__(16) float g_S[4 * NE_];   // S0, SA, S1, S2  (0.1I + 0.45*M)
__device__ float g_dis[N_];
__device__ float g_logits[3];                  // logits / (0.6*ln2)

// ---------------- packed f32x2 helpers ----------------
static __device__ __forceinline__ u64 ffma2(u64 a, u64 b, u64 c) {
    u64 d;
    asm("fma.rn.f32x2 %0, %1, %2, %3;" : "=l"(d) : "l"(a), "l"(b), "l"(c));
    return d;
}
static __device__ __forceinline__ u64 fadd2(u64 a, u64 b) {
    u64 d;
    asm("add.rn.f32x2 %0, %1, %2;" : "=l"(d) : "l"(a), "l"(b));
    return d;
}
static __device__ __forceinline__ u64 dup2(float v) {
    u64 d; unsigned u = __float_as_uint(v);
    asm("mov.b64 %0, {%1, %1};" : "=l"(d) : "r"(u));
    return d;
}
static __device__ __forceinline__ float2 unpack2(u64 v) {
    unsigned lo, hi;
    asm("mov.b64 {%0, %1}, %2;" : "=r"(lo), "=r"(hi) : "l"(v));
    return make_float2(__uint_as_float(lo), __uint_as_float(hi));
}

// ---------------- FMA-pipe transcendentals (no MUFU, no software powf) --------
static __device__ __forceinline__ float fast_lg2(float x) {
    int b = __float_as_int(x);
    int i = (b - 0x3f3504f3) & 0xff800000;
    float m = __int_as_float(b - i);
    float e = (float)(i >> 23);
    float t = m - 1.0f, z = t * t;
    float p =  7.0376836292e-2f;
    p = p * t - 1.1514610310e-1f;
    p = p * t + 1.1676998740e-1f;
    p = p * t - 1.2420140846e-1f;
    p = p * t + 1.4249322787e-1f;
    p = p * t - 1.6668057665e-1f;
    p = p * t + 2.0000714765e-1f;
    p = p * t - 2.4999993993e-1f;
    p = p * t + 3.3333331174e-1f;
    float lnm = t + (t * z * p - 0.5f * z);
    return e + lnm * 1.4426950409f;
}
static __device__ __forceinline__ float fast_ex2(float v) {
    v = fminf(fmaxf(v, -100.0f), 100.0f);
    int iv = __float2int_rd(v);
    float f = v - (float)iv;
    float p = 1.52527338e-5f;
    p = p * f + 1.54035304e-4f;
    p = p * f + 1.33335581e-3f;
    p = p * f + 9.61812911e-3f;
    p = p * f + 5.55041087e-2f;
    p = p * f + 2.40226507e-1f;
    p = p * f + 6.93147181e-1f;
    p = p * f + 1.0f;
    return p * __int_as_float((iv + 127) << 23);
}
static __device__ __forceinline__ float fast_rcp(float d) {
    float r = __int_as_float(0x7EF311C3 - __float_as_int(d));
    r = r * (2.0f - d * r);
    r = r * (2.0f - d * r);
    r = r * (2.0f - d * r);
    return r;
}
static __device__ float digamma_f(float x) {
    float r = 0.0f;
    while (x < 8.0f) { r -= fast_rcp(x); x += 1.0f; }
    float f = fast_rcp(x * x);
    float s = f * (1.0f / 12.0f - f * (1.0f / 120.0f - f * (1.0f / 252.0f
            - f * (1.0f / 240.0f - f * (1.0f / 132.0f)))));
    return r + 0.6931471806f * fast_lg2(x) - 0.5f * fast_rcp(x) - s;
}

// ---------------- kernel 1: degree/dis (32 blocks) + fast scalar block (32) ---
__global__ void __launch_bounds__(256) deg_scalar_kernel(
        const float* __restrict__ ewp,
        const float* __restrict__ a_uc,
        const float* __restrict__ b_uc,
        const float* __restrict__ u_pi,
        float* __restrict__ out) {
    int b = blockIdx.x, t = threadIdx.x;
    if (b == 32) {
        __shared__ float kld_s[3];
        if (t < 3) {
            const float LOG2E = 1.4426950409f, LN2 = 0.6931471806f;
            float au = fmaxf(a_uc[t], -10.f);
            float bu = fminf(fmaxf(b_uc[t], -10.f), 50.f);
            float a  = LN2 * fast_lg2(1.f + fast_ex2(au * LOG2E));
            float bb = LN2 * fast_lg2(1.f + fast_ex2(bu * LOG2E));
            float up = fminf(fmaxf(u_pi[t], 1e-6f), 1.f - 1e-6f);
            float t1 = fast_ex2(fast_lg2(up) * fast_rcp(bb));        // up^(1/b)
            float pi = fast_ex2(fast_lg2(1.f - t1) * fast_rcp(a));   // (...)^(1/a)
            g_logits[t] = (fast_lg2(pi) - fast_lg2(1.f - pi)) * (1.f / 0.6f);
            out[193 + t] = pi;   // drop_rates
            const float euler = 0.577215664901532f;
            kld_s[t] = (1.f - 0.8f * fast_rcp(a)) * (-euler - digamma_f(bb) - fast_rcp(bb))
                     + LN2 * fast_lg2(a * bb + 1e-10f) + 0.22314355f
                     - (bb - 1.f) * fast_rcp(bb);
        }
        __syncthreads();
        if (t == 0) out[192] = kld_s[0] + kld_s[1] + kld_s[2];   // kld_loss
        return;
    }
    int w = t >> 5, l = t & 31;
    int r = b * 8 + w;
    float s = 0.f;
    #pragma unroll
    for (int jj = 0; jj < 8; jj++) {
        int j = l + jj * 32;
        int hi = max(r, j), lo = min(r, j);
        s += fabsf(ewp[(hi * (hi + 1)) / 2 + lo]);
    }
    #pragma unroll
    for (int o = 16; o > 0; o >>= 1) s += __shfl_xor_sync(0xffffffffu, s, o);
    if (l == 0) g_dis[r] = (s > 0.f) ? rsqrtf(s) : 0.f;
}

// ---------------- kernel 2: build S matrices (0.1I + 0.45*M), fast sigmoid ----
__global__ void __launch_bounds__(256) mats_kernel(const float* __restrict__ ewp,
                                                   const float* __restrict__ u_rb) {
    int i = blockIdx.x, j = threadIdx.x;
    int r = max(i, j), c = min(i, j);
    float w = ewp[(r * (r + 1)) / 2 + c];
    float aij = g_dis[i] * w * g_dis[j];
    int e = i * N_ + j;
    float diag = (i == j) ? 0.1f : 0.0f;
    g_S[1 * NE_ + e] = 0.45f * aij + diag;                        // SA
    #pragma unroll
    for (int l = 0; l < 3; l++) {
        float ur = u_rb[l * NE_ + e];
        ur = fminf(fmaxf(ur, 1e-6f), 1.0f - 1e-6f);
        float L = (fast_lg2(ur) - fast_lg2(1.0f - ur)) * (1.0f / 0.6f);
        float v = -(g_logits[l] + L);
        float z = fast_rcp(1.0f + fast_ex2(v));
        int slot = (l == 0) ? 0 : (l + 1);                        // S0, S1, S2
        g_S[slot * NE_ + e] = 0.45f * z * aij + diag;
    }
}

// ---------------- kernel 3: 5 direct conv stages + head, L2-streamed M --------
// 128 blocks = (graph b = blockIdx.x>>1, col-half c = blockIdx.x&1),
// cluster (2,1,1), 512 threads. Matrices read straight from L2 via batched
// LDG.64 (no smem staging). X double-buffered in smem (dup2'd u64); the only
// cross-CTA dependency is the X exchange -> one cluster barrier per stage.
// Thread t: j2 = t&63 (col pair within the 128-col half), q = t>>6 (8-way
// k-split of 32 rows). 8-way combine, relu on stage 2.
__global__ void __launch_bounds__(512, 1) __cluster_dims__(2, 1, 1)
conv5_head_kernel(const float* __restrict__ x,
                  const float* __restrict__ lin_w, const float* __restrict__ lin_b,
                  const float* __restrict__ fc_w,  const float* __restrict__ fc_b,
                  float* __restrict__ out) {
    __shared__ __align__(16) u64 Xd[2][N_ * 6];     // 2 x 12288 B (stride 6 for LDS.128 align)
    __shared__ __align__(16) u64 Ps[8 * 321];       // 20544 B (aliased as Pool in head)
    __shared__ float PoolP[128];

    const int t  = threadIdx.x;
    const int b  = blockIdx.x >> 1;
    const int c  = blockIdx.x & 1;
    const int q  = t >> 6;           // warp-uniform k-split 0..7
    const int j2 = t & 63;           // col pair 0..63
    const unsigned prank = (unsigned)(c ^ 1);

    // load full X for this graph into buffer 0 (dup2'd)
    {
        const float* xb = x + b * (N_ * FIN);
        for (int idx = t; idx < N_ * FIN; idx += 512) {
            int n = idx / 5, f = idx - n * 5;
            Xd[0][n * 6 + f] = dup2(xb[idx]);
        }
    }

    // peer smem windows (both X buffers + PoolP)
    unsigned peerX0, peerX1, peerPP;
    {
        unsigned l0 = (unsigned)__cvta_generic_to_shared(&Xd[0][0]);
        unsigned l1 = (unsigned)__cvta_generic_to_shared(&Xd[1][0]);
        unsigned lp = (unsigned)__cvta_generic_to_shared(&PoolP[0]);
        asm("mapa.shared::cluster.u32 %0, %1, %2;" : "=r"(peerX0) : "r"(l0), "r"(prank));
        asm("mapa.shared::cluster.u32 %0, %1, %2;" : "=r"(peerX1) : "r"(l1), "r"(prank));
        asm("mapa.shared::cluster.u32 %0, %1, %2;" : "=r"(peerPP) : "r"(lp), "r"(prank));
    }

    const float* Ms[5] = { g_S, g_S + NE_, g_S + 2 * NE_, g_S + NE_, g_S + 3 * NE_ };
    __syncthreads();

    #pragma unroll 1
    for (int s = 0; s < 5; s++) {
        const int rb = s & 1;                 // read buffer
        const int wb = rb ^ 1;                // write buffer
        const float* Msrc = Ms[s] + c * 128;  // this CTA's 128 columns
        const u64* XR = &Xd[rb][0];

        u64 acc0 = 0, acc1 = 0, acc2 = 0, acc3 = 0, acc4 = 0;
        const int k0 = q * 32;
        #pragma unroll 1
        for (int kk = 0; kk < 32; kk += 8) {
            u64 m[8];
            #pragma unroll
            for (int u = 0; u < 8; u++)
                m[u] = *((const u64*)(Msrc + (k0 + kk + u) * 256) + j2);   // LDG.64 x8, MLP=8
            #pragma unroll
            for (int u = 0; u < 8; u++) {
                const u64* xr = &XR[(k0 + kk + u) * 6];
                ulonglong2 xa = *(const ulonglong2*)xr;          // feats 0,1 (broadcast)
                ulonglong2 xb = *(const ulonglong2*)(xr + 2);    // feats 2,3
                u64        x4 = xr[4];                           // feat 4
                acc0 = ffma2(m[u], xa.x, acc0);
                acc1 = ffma2(m[u], xa.y, acc1);
                acc2 = ffma2(m[u], xb.x, acc2);
                acc3 = ffma2(m[u], xb.y, acc3);
                acc4 = ffma2(m[u], x4,  acc4);
            }
        }
        // stash partials: entry e = j2*5+f, slot q
        {
            u64* pp = &Ps[q * 321 + j2 * 5];
            pp[0] = acc0; pp[1] = acc1; pp[2] = acc2; pp[3] = acc3; pp[4] = acc4;
        }
        __syncthreads();

        // combine 8 k-splits, relu on stage 2, write new X (local + peer)
        if (t < 320) {
            u64 sum = Ps[t];
            #pragma unroll
            for (int qq = 1; qq < 8; qq++) sum = fadd2(sum, Ps[qq * 321 + t]);
            float2 sv = unpack2(sum);
            if (s == 2) { sv.x = fmaxf(sv.x, 0.f); sv.y = fmaxf(sv.y, 0.f); }
            int j2c = t / 5, f = t - j2c * 5;
            int g0 = c * 128 + 2 * j2c;
            u64 d0 = dup2(sv.x), d1 = dup2(sv.y);
            Xd[wb][g0 * 6 + f] = d0;
            Xd[wb][(g0 + 1) * 6 + f] = d1;
            if (s < 4) {   // head only needs local half after the last stage
                unsigned pbase = wb ? peerX1 : peerX0;
                asm volatile("st.shared::cluster.b64 [%0], %1;"
                             :: "r"(pbase + (g0 * 6 + f) * 8), "l"(d0));
                asm volatile("st.shared::cluster.b64 [%0], %1;"
                             :: "r"(pbase + ((g0 + 1) * 6 + f) * 8), "l"(d1));
            }
        }
        if (s < 4) {
            asm volatile("barrier.cluster.arrive.aligned;" ::: "memory");
            asm volatile("barrier.cluster.wait.aligned;" ::: "memory");
        } else {
            __syncthreads();
        }
    }

    // ---- head: relu(o @ lin_w + lin_b), pool over this CTA's 128 nodes -------
    // final output lives in Xd[1] (stage 4 wrote buffer 1); read low 32 bits
    {
        const unsigned* O32 = (const unsigned*)&Xd[1][0];
        float* Pool = (float*)Ps;                     // [4][128]
        int k = t & 127, h = t >> 7;
        float lw0 = lin_w[k], lw1 = lin_w[128 + k], lw2 = lin_w[256 + k],
              lw3 = lin_w[384 + k], lw4 = lin_w[512 + k];
        float lb = lin_b[k];
        float s2 = 0.f;
        int n0 = c * 128 + h * 32;
        for (int n = n0; n < n0 + 32; n++) {
            const unsigned* xr = &O32[(n * 6) * 2];
            float v = lb;
            v = fmaf(__uint_as_float(xr[0]), lw0, v);
            v = fmaf(__uint_as_float(xr[2]), lw1, v);
            v = fmaf(__uint_as_float(xr[4]), lw2, v);
            v = fmaf(__uint_as_float(xr[6]), lw3, v);
            v = fmaf(__uint_as_float(xr[8]), lw4, v);
            s2 += fmaxf(v, 0.f);
        }
        Pool[h * 128 + k] = s2;
    }
    __syncthreads();
    {
        float* Pool = (float*)Ps;
        if (t < 128) {
            float p = Pool[t] + Pool[128 + t] + Pool[256 + t] + Pool[384 + t];
            if (c) {
                asm volatile("st.shared::cluster.f32 [%0], %1;"
                             :: "r"(peerPP + t * 4), "f"(p));
            } else {
                Pool[t] = p;
            }
        }
        asm volatile("barrier.cluster.arrive.aligned;" ::: "memory");
        asm volatile("barrier.cluster.wait.aligned;" ::: "memory");
        if (c == 0 && t < 3) {
            float s2 = fc_b[t];
            for (int k2 = 0; k2 < 128; k2++)
                s2 = fmaf(Pool[k2] + PoolP[k2], fc_w[k2 * 3 + t], s2);
            out[b * 3 + t] = s2;
        }
    }
}

// ---------------- launch ----------------
extern "C" void kernel_launch(void* const* d_in, const int* in_sizes, int n_in,
                              void* d_out, int out_size) {
    const float* x     = (const float*)d_in[0];
    const float* ewp   = (const float*)d_in[1];
    const float* a_uc  = (const float*)d_in[2];
    const float* b_uc  = (const float*)d_in[3];
    const float* u_pi  = (const float*)d_in[4];
    const float* u_rb  = (const float*)d_in[5];
    const float* lin_w = (const float*)d_in[6];
    const float* lin_b = (const float*)d_in[7];
    const float* fc_w  = (const float*)d_in[8];
    const float* fc_b  = (const float*)d_in[9];
    // d_in[10] = edge_index, d_in[11] = batch: structure is analytic, unused.
    float* out = (float*)d_out;

    deg_scalar_kernel<<<33, 256>>>(ewp, a_uc, b_uc, u_pi, out);
    mats_kernel<<<N_, 256>>>(ewp, u_rb);
    conv5_head_kernel<<<2 * B_, 512>>>(x, lin_w, lin_b, fc_w, fc_b, out);
}